// round 11
// baseline (speedup 1.0000x reference)
#include <cuda_runtime.h>
#include <cuda_bf16.h>
#include <cstdint>

#define DVAL 64
#define MAXM 16384
#define MAXN 8192
#define REGP   0.05f
#define LOG2E  1.4426950408889634f
#define LN2    0.6931471805599453f
#define SHIFT  28.0f

#define THREADS 128          // 4 warps
#define BLOCK_ROWS 128       // 32 rows per warp
#define TJ 128               // j-tile
#define JSPLIT 11
#define MAXTILES 12          // ceil(128/11)
#define ONESF 0x3F803F80u    // bf16x2 (1.0, 1.0)

__device__ double g_cost_sum;
__device__ double g_psi_sum;
__device__ double g_result;
__device__ unsigned int g_done;
__device__ float  g_sqt[MAXM];
__device__ float  g_sqs[MAXN];
__device__ float  g_rowsum[MAXN];
__device__ uint32_t g_tgtb[MAXM * DVAL / 2];   // bf16x2 packed
__device__ uint32_t g_srcb[MAXN * DVAL / 2];

// ---------- helpers ----------
static __device__ __forceinline__ uint32_t cvt_bf16x2(float lo, float hi) {
    uint32_t r; asm("cvt.rn.bf16x2.f32 %0, %1, %2;" : "=r"(r) : "f"(hi), "f"(lo)); return r;
}
static __device__ __forceinline__ uint32_t ex2_bf16x2(uint32_t a) {
    uint32_t r; asm("ex2.approx.ftz.bf16x2 %0, %1;" : "=r"(r) : "r"(a)); return r;
}
// D += A*B (C == D)
static __device__ __forceinline__ void mma16816(float* c, const uint32_t* a, uint32_t b0, uint32_t b1) {
    asm("mma.sync.aligned.m16n8k16.row.col.f32.bf16.bf16.f32 "
        "{%0,%1,%2,%3}, {%4,%5,%6,%7}, {%8,%9}, {%0,%1,%2,%3};"
        : "+f"(c[0]), "+f"(c[1]), "+f"(c[2]), "+f"(c[3])
        : "r"(a[0]), "r"(a[1]), "r"(a[2]), "r"(a[3]), "r"(b0), "r"(b1));
}
// D = A*B + C (separate C: bias-fused first k-step)
static __device__ __forceinline__ void mma16816_dc(float* d, const uint32_t* a, uint32_t b0, uint32_t b1,
                                                   const float* c) {
    asm("mma.sync.aligned.m16n8k16.row.col.f32.bf16.bf16.f32 "
        "{%0,%1,%2,%3}, {%4,%5,%6,%7}, {%8,%9}, {%10,%11,%12,%13};"
        : "=f"(d[0]), "=f"(d[1]), "=f"(d[2]), "=f"(d[3])
        : "r"(a[0]), "r"(a[1]), "r"(a[2]), "r"(a[3]), "r"(b0), "r"(b1),
          "f"(c[0]), "f"(c[1]), "f"(c[2]), "f"(c[3]));
}
static __device__ __forceinline__ void ldm_x4(uint32_t* r, uint32_t addr) {
    asm volatile("ldmatrix.sync.aligned.m8n8.x4.shared.b16 {%0,%1,%2,%3}, [%4];"
        : "=r"(r[0]), "=r"(r[1]), "=r"(r[2]), "=r"(r[3]) : "r"(addr));
}
static __device__ __forceinline__ uint32_t smem_u32(const void* p) {
    uint32_t a;
    asm("{ .reg .u64 t; cvta.to.shared.u64 t, %1; cvt.u32.u64 %0, t; }" : "=r"(a) : "l"(p));
    return a;
}
#define CP_ASYNC16(dst, src) \
    asm volatile("cp.async.cg.shared.global [%0], [%1], 16;" :: "r"(dst), "l"(src) : "memory")
#define CP_COMMIT() asm volatile("cp.async.commit_group;" ::: "memory")
#define CP_WAIT0()  asm volatile("cp.async.wait_group 0;" ::: "memory")

// ---------------- kernel 1: convert + reductions + init ----------------
__global__ void k_pre(const float* __restrict__ src, const float* __restrict__ tgt,
                      const float* __restrict__ psi, int N, int M) {
    int gtid = blockIdx.x * blockDim.x + threadIdx.x;
    int nth  = gridDim.x * blockDim.x;
    int lane = threadIdx.x & 31;

    if (gtid == 0) { g_cost_sum = 0.0; g_psi_sum = 0.0; g_result = 0.0; g_done = 0u; }
    for (int i = gtid; i < N; i += nth) g_rowsum[i] = 0.0f;

    const float2* t2 = (const float2*)tgt;
    float cs = 0.0f;
    for (int i = gtid; i < M * 32; i += nth) {
        float2 v = t2[i];
        cs += v.x * v.x + v.y * v.y;
        g_tgtb[i] = cvt_bf16x2(v.x, v.y);
    }
    const float2* s2 = (const float2*)src;
    for (int i = gtid; i < N * 32; i += nth) {
        float2 v = s2[i];
        g_srcb[i] = cvt_bf16x2(v.x, v.y);
    }
    float pp = 0.0f;
    for (int i = gtid; i < M; i += nth) pp += psi[i];
    #pragma unroll
    for (int o = 16; o; o >>= 1) {
        cs += __shfl_xor_sync(0xffffffffu, cs, o);
        pp += __shfl_xor_sync(0xffffffffu, pp, o);
    }
    if (lane == 0) {
        atomicAdd(&g_cost_sum, (double)cs);
        if (pp != 0.0f) atomicAdd(&g_psi_sum, (double)pp);
    }

    // per-row squared norms, 4 lanes per row
    int grp = gtid >> 2, sub = gtid & 3, ngrp = nth >> 2;
    for (int row = grp; row < M + N; row += ngrp) {
        const float4* p = (row < M)
            ? (const float4*)(tgt + (size_t)row * DVAL)
            : (const float4*)(src + (size_t)(row - M) * DVAL);
        float s = 0.0f;
        #pragma unroll
        for (int q = 0; q < 4; ++q) {
            float4 v = p[sub + q * 4];
            s += v.x * v.x + v.y * v.y + v.z * v.z + v.w * v.w;
        }
        s += __shfl_xor_sync(0xffffffffu, s, 1);
        s += __shfl_xor_sync(0xffffffffu, s, 2);
        if (sub == 0) {
            if (row < M) g_sqt[row] = s; else g_sqs[row - M] = s;
        }
    }
}

// ---------------- kernel 2: main HMMA + bf16x2 exp2 + mma-reduction ----------------
__global__ void __launch_bounds__(THREADS, 5)
k_main_mma(const float* __restrict__ psi, float* __restrict__ out, int N, int M) {
    __shared__ char sm[2 * 16384 + MAXTILES * TJ * 4];
    __shared__ int smflag;
    float* sbias = (float*)(sm + 32768);
    const uint32_t smb = smem_u32(sm);

    const int tid  = threadIdx.x;
    const int wid  = tid >> 5;
    const int lane = tid & 31;
    const int g    = lane >> 2;

    const int rbase = blockIdx.x * BLOCK_ROWS + wid * 32;

    const int TT = M / TJ;
    const int tbeg = (blockIdx.y * TT) / JSPLIT;
    const int tend = ((blockIdx.y + 1) * TT) / JSPLIT;
    const int jbase = tbeg * TJ;
    const int jcnt  = (tend - tbeg) * TJ;

    const char* tgtb_bytes = (const char*)g_tgtb;

    // ---- start tile 0 fill: 8 x 16B chunks per thread ----
    #pragma unroll
    for (int q = 0; q < 8; ++q) {
        int ch = tid + q * THREADS, r = ch >> 3, c = ch & 7;
        uint32_t dsw = (uint32_t)((r * 128 + c * 16) ^ ((r & 7) << 4));
        CP_ASYNC16(smb + dsw, tgtb_bytes + (size_t)(jbase + r) * 128 + c * 16);
    }
    CP_COMMIT();

    const float cn = (float)(g_cost_sum / (double)M);
    const float alpha = 1.0f / (REGP * cn);
    const float k1 = 2.0f * LOG2E * alpha;

    // ---- bias for whole j-range into smem (overlaps cp.async) ----
    for (int jj = tid; jj < jcnt; jj += THREADS) {
        int j = jbase + jj;
        sbias[jj] = LOG2E * (psi[j] * (1.0f / REGP) - alpha * g_sqt[j]) + SHIFT;
    }

    // ---- A fragments from bf16 globals, prescaled by k1 (f32 mul, re-round) ----
    uint32_t afr[2][4][4];
    {
        const uint32_t* xb = g_srcb + (size_t)rbase * 32;
        #pragma unroll
        for (int t = 0; t < 2; ++t) {
            #pragma unroll
            for (int ks = 0; ks < 4; ++ks) {
                const uint32_t* p = xb + (t * 16 + g) * 32 + ks * 8 + (lane & 3);
                afr[t][ks][0] = p[0];
                afr[t][ks][1] = p[256];
                afr[t][ks][2] = p[4];
                afr[t][ks][3] = p[260];
                #pragma unroll
                for (int i = 0; i < 4; ++i) {
                    uint32_t u = afr[t][ks][i];
                    float lo = __uint_as_float(u << 16);
                    float hi = __uint_as_float(u & 0xFFFF0000u);
                    afr[t][ks][i] = cvt_bf16x2(lo * k1, hi * k1);
                }
            }
        }
    }

    // ldmatrix per-lane addresses (s-invariant swizzle)
    const int lr = lane & 7, lq = lane >> 3;
    const uint32_t lmoff0 = (uint32_t)(lr * 128 + ((lq * 16)       ^ (lr << 4)));
    const uint32_t lmoff1 = (uint32_t)(lr * 128 + (((lq + 4) * 16) ^ (lr << 4)));
    const int biasoff = (lane & 3) * 2;

    // f32 row-sum accumulators fed by the reduction MMA
    float acc0[4] = {0.f, 0.f, 0.f, 0.f};   // rows g, g+8
    float acc1[4] = {0.f, 0.f, 0.f, 0.f};   // rows g+16, g+24

    for (int t = tbeg; t < tend; ++t) {
        const int cur = (t - tbeg) & 1, nxt = cur ^ 1;
        const bool more = (t + 1 < tend);

        CP_WAIT0();
        __syncthreads();

        if (more) {
            int j0 = (t + 1) * TJ;
            uint32_t dst = smb + (uint32_t)(nxt * 16384);
            #pragma unroll
            for (int q = 0; q < 8; ++q) {
                int ch = tid + q * THREADS, r = ch >> 3, c = ch & 7;
                uint32_t dsw = (uint32_t)((r * 128 + c * 16) ^ ((r & 7) << 4));
                CP_ASYNC16(dst + dsw, tgtb_bytes + (size_t)(j0 + r) * 128 + c * 16);
            }
            CP_COMMIT();
        }

        const uint32_t tadd = smb + (uint32_t)(cur * 16384);
        const float* bb = sbias + (t - tbeg) * TJ;
        #pragma unroll 2
        for (int sp = 0; sp < 8; ++sp) {
            uint32_t eA[4], eB[4];   // bf16x2 exps: A-fragments for reduction mma
            #pragma unroll
            for (int h = 0; h < 2; ++h) {
                const int s = sp * 2 + h;
                const float2 bp = *(const float2*)(bb + s * 8 + biasoff);
                const float bias4[4] = { bp.x, bp.y, bp.x, bp.y };
                float c0f[4], c1f[4];
                uint32_t bA[4], bB[4];
                ldm_x4(bA, tadd + s * 1024 + lmoff0);
                ldm_x4(bB, tadd + s * 1024 + lmoff1);
                // first k-step fuses bias via C-operand; rest accumulate
                mma16816_dc(c0f, afr[0][0], bA[0], bA[1], bias4);
                mma16816_dc(c1f, afr[1][0], bA[0], bA[1], bias4);
                mma16816(c0f, afr[0][1], bA[2], bA[3]);
                mma16816(c1f, afr[1][1], bA[2], bA[3]);
                mma16816(c0f, afr[0][2], bB[0], bB[1]);
                mma16816(c1f, afr[1][2], bB[0], bB[1]);
                mma16816(c0f, afr[0][3], bB[2], bB[3]);
                mma16816(c1f, afr[1][3], bB[2], bB[3]);

                eA[h * 2 + 0] = ex2_bf16x2(cvt_bf16x2(c0f[0], c0f[1]));   // row g
                eA[h * 2 + 1] = ex2_bf16x2(cvt_bf16x2(c0f[2], c0f[3]));   // row g+8
                eB[h * 2 + 0] = ex2_bf16x2(cvt_bf16x2(c1f[0], c1f[1]));   // row g+16
                eB[h * 2 + 1] = ex2_bf16x2(cvt_bf16x2(c1f[2], c1f[3]));   // row g+24
            }
            // row-sum via tensor pipe: C[m,n] += sum_k E[m,k] * 1
            mma16816(acc0, eA, ONESF, ONESF);
            mma16816(acc1, eB, ONESF, ONESF);
        }
        __syncthreads();
    }

    // ---- per-row accumulation: acc[0]/acc[2] hold full row sums (4 lanes identical) ----
    if ((lane & 3) == 0) {
        atomicAdd(&g_rowsum[rbase + g],      acc0[0]);
        atomicAdd(&g_rowsum[rbase + 8 + g],  acc0[2]);
        atomicAdd(&g_rowsum[rbase + 16 + g], acc1[0]);
        atomicAdd(&g_rowsum[rbase + 24 + g], acc1[2]);
    }

    // ---- inline finalize: last CTA reduces all rows ----
    __syncthreads();
    if (tid == 0) {
        __threadfence();
        unsigned int old = atomicAdd(&g_done, 1u);
        smflag = (old == (unsigned int)(gridDim.x * gridDim.y - 1)) ? 1 : 0;
    }
    __syncthreads();
    if (smflag) {
        const float log_nu = -logf((float)M);
        double part = 0.0;
        for (int i = tid; i < N; i += THREADS) {
            float lse = -alpha * g_sqs[i] + log_nu + LN2 * (log2f(g_rowsum[i]) - SHIFT);
            part += (double)(-REGP * lse);
        }
        #pragma unroll
        for (int o = 16; o; o >>= 1) part += __shfl_xor_sync(0xffffffffu, part, o);
        if (lane == 0) atomicAdd(&g_result, part);
        __syncthreads();
        if (tid == 0)
            out[0] = (float)(g_result / (double)N + g_psi_sum / (double)M);
    }
}

extern "C" void kernel_launch(void* const* d_in, const int* in_sizes, int n_in,
                              void* d_out, int out_size) {
    const float* src = (const float*)d_in[0];   // [N, 64]
    const float* tgt = (const float*)d_in[1];   // [M, 64]
    const float* psi = (const float*)d_in[2];   // [M]
    int N = in_sizes[0] / DVAL;
    int M = in_sizes[2];

    k_pre<<<296, 256>>>(src, tgt, psi, N, M);

    dim3 grd(N / BLOCK_ROWS, JSPLIT);           // 64 x 11 = 704 CTAs, ~5/SM in one wave
    k_main_mma<<<grd, THREADS>>>(psi, (float*)d_out, N, M);
}

// round 12
// speedup vs baseline: 1.0672x; 1.0672x over previous
#include <cuda_runtime.h>
#include <cuda_bf16.h>
#include <cstdint>

#define DVAL 64
#define MAXM 16384
#define MAXN 8192
#define REGP   0.05f
#define LOG2E  1.4426950408889634f
#define LN2    0.6931471805599453f
#define SHIFT  28.0f

#define THREADS 512          // 16 warps
#define BLOCK_ROWS 512       // 32 rows per warp
#define TJ 128               // j-tile
#define JSPLIT 9
#define MAXTILES 15          // ceil(128/9)
#define ONESF 0x3F803F80u    // bf16x2 (1.0, 1.0)

__device__ double g_cost_sum;
__device__ double g_psi_sum;
__device__ double g_result;
__device__ unsigned int g_done;
__device__ float  g_sqt[MAXM];
__device__ float  g_sqs[MAXN];
__device__ float  g_rowsum[MAXN];
__device__ uint32_t g_tgtb[MAXM * DVAL / 2];   // bf16x2 packed
__device__ uint32_t g_srcb[MAXN * DVAL / 2];

// ---------- helpers ----------
static __device__ __forceinline__ uint32_t cvt_bf16x2(float lo, float hi) {
    uint32_t r; asm("cvt.rn.bf16x2.f32 %0, %1, %2;" : "=r"(r) : "f"(hi), "f"(lo)); return r;
}
static __device__ __forceinline__ uint32_t ex2_bf16x2(uint32_t a) {
    uint32_t r; asm("ex2.approx.ftz.bf16x2 %0, %1;" : "=r"(r) : "r"(a)); return r;
}
// D += A*B (C == D)
static __device__ __forceinline__ void mma16816(float* c, const uint32_t* a, uint32_t b0, uint32_t b1) {
    asm("mma.sync.aligned.m16n8k16.row.col.f32.bf16.bf16.f32 "
        "{%0,%1,%2,%3}, {%4,%5,%6,%7}, {%8,%9}, {%0,%1,%2,%3};"
        : "+f"(c[0]), "+f"(c[1]), "+f"(c[2]), "+f"(c[3])
        : "r"(a[0]), "r"(a[1]), "r"(a[2]), "r"(a[3]), "r"(b0), "r"(b1));
}
// D = A*B + C (separate C: bias-fused first k-step)
static __device__ __forceinline__ void mma16816_dc(float* d, const uint32_t* a, uint32_t b0, uint32_t b1,
                                                   const float* c) {
    asm("mma.sync.aligned.m16n8k16.row.col.f32.bf16.bf16.f32 "
        "{%0,%1,%2,%3}, {%4,%5,%6,%7}, {%8,%9}, {%10,%11,%12,%13};"
        : "=f"(d[0]), "=f"(d[1]), "=f"(d[2]), "=f"(d[3])
        : "r"(a[0]), "r"(a[1]), "r"(a[2]), "r"(a[3]), "r"(b0), "r"(b1),
          "f"(c[0]), "f"(c[1]), "f"(c[2]), "f"(c[3]));
}
static __device__ __forceinline__ void ldm_x4(uint32_t* r, uint32_t addr) {
    asm volatile("ldmatrix.sync.aligned.m8n8.x4.shared.b16 {%0,%1,%2,%3}, [%4];"
        : "=r"(r[0]), "=r"(r[1]), "=r"(r[2]), "=r"(r[3]) : "r"(addr));
}
static __device__ __forceinline__ uint32_t smem_u32(const void* p) {
    uint32_t a;
    asm("{ .reg .u64 t; cvta.to.shared.u64 t, %1; cvt.u32.u64 %0, t; }" : "=r"(a) : "l"(p));
    return a;
}
#define CP_ASYNC16(dst, src) \
    asm volatile("cp.async.cg.shared.global [%0], [%1], 16;" :: "r"(dst), "l"(src) : "memory")
#define CP_COMMIT() asm volatile("cp.async.commit_group;" ::: "memory")
#define CP_WAIT0()  asm volatile("cp.async.wait_group 0;" ::: "memory")

// ---------------- kernel 1: convert + reductions + init ----------------
__global__ void k_pre(const float* __restrict__ src, const float* __restrict__ tgt,
                      const float* __restrict__ psi, int N, int M) {
    int gtid = blockIdx.x * blockDim.x + threadIdx.x;
    int nth  = gridDim.x * blockDim.x;
    int lane = threadIdx.x & 31;

    if (gtid == 0) { g_cost_sum = 0.0; g_psi_sum = 0.0; g_result = 0.0; g_done = 0u; }
    for (int i = gtid; i < N; i += nth) g_rowsum[i] = 0.0f;

    const float2* t2 = (const float2*)tgt;
    float cs = 0.0f;
    for (int i = gtid; i < M * 32; i += nth) {
        float2 v = t2[i];
        cs += v.x * v.x + v.y * v.y;
        g_tgtb[i] = cvt_bf16x2(v.x, v.y);
    }
    const float2* s2 = (const float2*)src;
    for (int i = gtid; i < N * 32; i += nth) {
        float2 v = s2[i];
        g_srcb[i] = cvt_bf16x2(v.x, v.y);
    }
    float pp = 0.0f;
    for (int i = gtid; i < M; i += nth) pp += psi[i];
    #pragma unroll
    for (int o = 16; o; o >>= 1) {
        cs += __shfl_xor_sync(0xffffffffu, cs, o);
        pp += __shfl_xor_sync(0xffffffffu, pp, o);
    }
    if (lane == 0) {
        atomicAdd(&g_cost_sum, (double)cs);
        if (pp != 0.0f) atomicAdd(&g_psi_sum, (double)pp);
    }

    // per-row squared norms, 4 lanes per row
    int grp = gtid >> 2, sub = gtid & 3, ngrp = nth >> 2;
    for (int row = grp; row < M + N; row += ngrp) {
        const float4* p = (row < M)
            ? (const float4*)(tgt + (size_t)row * DVAL)
            : (const float4*)(src + (size_t)(row - M) * DVAL);
        float s = 0.0f;
        #pragma unroll
        for (int q = 0; q < 4; ++q) {
            float4 v = p[sub + q * 4];
            s += v.x * v.x + v.y * v.y + v.z * v.z + v.w * v.w;
        }
        s += __shfl_xor_sync(0xffffffffu, s, 1);
        s += __shfl_xor_sync(0xffffffffu, s, 2);
        if (sub == 0) {
            if (row < M) g_sqt[row] = s; else g_sqs[row - M] = s;
        }
    }
}

// ---------------- kernel 2: main HMMA + bf16x2 exp2 + mma-reduction ----------------
__global__ void __launch_bounds__(THREADS, 1)
k_main_mma(const float* __restrict__ psi, float* __restrict__ out, int N, int M) {
    __shared__ char sm[2 * 16384 + MAXTILES * TJ * 4];
    __shared__ int smflag;
    float* sbias = (float*)(sm + 32768);
    const uint32_t smb = smem_u32(sm);

    const int tid  = threadIdx.x;
    const int wid  = tid >> 5;
    const int lane = tid & 31;
    const int g    = lane >> 2;

    const int rbase = blockIdx.x * BLOCK_ROWS + wid * 32;

    const int TT = M / TJ;
    const int tbeg = (blockIdx.y * TT) / JSPLIT;
    const int tend = ((blockIdx.y + 1) * TT) / JSPLIT;
    const int jbase = tbeg * TJ;
    const int jcnt  = (tend - tbeg) * TJ;

    // per-thread cp.async chunk coords (2 chunks of 16B per thread)
    const int ch0 = tid,       r0 = ch0 >> 3, c0 = ch0 & 7;
    const int ch1 = tid + 512, r1 = ch1 >> 3, c1 = ch1 & 7;
    const uint32_t d0 = (uint32_t)((r0 * 128 + c0 * 16) ^ ((r0 & 7) << 4));
    const uint32_t d1 = (uint32_t)((r1 * 128 + c1 * 16) ^ ((r1 & 7) << 4));
    const char* tgtb_bytes = (const char*)g_tgtb;

    // ---- start tile 0 fill ----
    CP_ASYNC16(smb + d0, tgtb_bytes + (size_t)(jbase + r0) * 128 + c0 * 16);
    CP_ASYNC16(smb + d1, tgtb_bytes + (size_t)(jbase + r1) * 128 + c1 * 16);
    CP_COMMIT();

    const float cn = (float)(g_cost_sum / (double)M);
    const float alpha = 1.0f / (REGP * cn);
    const float k1 = 2.0f * LOG2E * alpha;

    // ---- bias for whole j-range into smem (overlaps cp.async) ----
    for (int jj = tid; jj < jcnt; jj += THREADS) {
        int j = jbase + jj;
        sbias[jj] = LOG2E * (psi[j] * (1.0f / REGP) - alpha * g_sqt[j]) + SHIFT;
    }

    // ---- A fragments from bf16 globals, prescaled by k1 ----
    uint32_t afr[2][4][4];
    {
        const uint32_t* xb = g_srcb + (size_t)rbase * 32;
        #pragma unroll
        for (int t = 0; t < 2; ++t) {
            #pragma unroll
            for (int ks = 0; ks < 4; ++ks) {
                const uint32_t* p = xb + (t * 16 + g) * 32 + ks * 8 + (lane & 3);
                afr[t][ks][0] = p[0];
                afr[t][ks][1] = p[256];
                afr[t][ks][2] = p[4];
                afr[t][ks][3] = p[260];
                #pragma unroll
                for (int i = 0; i < 4; ++i) {
                    uint32_t u = afr[t][ks][i];
                    float lo = __uint_as_float(u << 16);
                    float hi = __uint_as_float(u & 0xFFFF0000u);
                    afr[t][ks][i] = cvt_bf16x2(lo * k1, hi * k1);
                }
            }
        }
    }

    // ldmatrix per-lane addresses (s-invariant swizzle)
    const int lr = lane & 7, lq = lane >> 3;
    const uint32_t lmoff0 = (uint32_t)(lr * 128 + ((lq * 16)       ^ (lr << 4)));
    const uint32_t lmoff1 = (uint32_t)(lr * 128 + (((lq + 4) * 16) ^ (lr << 4)));
    const int biasoff = (lane & 3) * 2;

    // f32 row-sum accumulators fed by the reduction MMA
    float acc0[4] = {0.f, 0.f, 0.f, 0.f};   // rows g, g+8
    float acc1[4] = {0.f, 0.f, 0.f, 0.f};   // rows g+16, g+24

    for (int t = tbeg; t < tend; ++t) {
        const int cur = (t - tbeg) & 1, nxt = cur ^ 1;
        const bool more = (t + 1 < tend);

        CP_WAIT0();
        __syncthreads();

        if (more) {
            int j0 = (t + 1) * TJ;
            uint32_t dst = smb + (uint32_t)(nxt * 16384);
            CP_ASYNC16(dst + d0, tgtb_bytes + (size_t)(j0 + r0) * 128 + c0 * 16);
            CP_ASYNC16(dst + d1, tgtb_bytes + (size_t)(j0 + r1) * 128 + c1 * 16);
            CP_COMMIT();
        }

        const uint32_t tadd = smb + (uint32_t)(cur * 16384);
        const float* bb = sbias + (t - tbeg) * TJ;
        #pragma unroll 2
        for (int sp = 0; sp < 8; ++sp) {
            uint32_t eA[4], eB[4];   // bf16x2 exps: A-fragments for reduction mma
            #pragma unroll
            for (int h = 0; h < 2; ++h) {
                const int s = sp * 2 + h;
                const float2 bp = *(const float2*)(bb + s * 8 + biasoff);
                const float bias4[4] = { bp.x, bp.y, bp.x, bp.y };
                float c0f[4], c1f[4];
                uint32_t bA[4], bB[4];
                ldm_x4(bA, tadd + s * 1024 + lmoff0);
                ldm_x4(bB, tadd + s * 1024 + lmoff1);
                // first k-step fuses bias via C-operand; rest accumulate
                mma16816_dc(c0f, afr[0][0], bA[0], bA[1], bias4);
                mma16816_dc(c1f, afr[1][0], bA[0], bA[1], bias4);
                mma16816(c0f, afr[0][1], bA[2], bA[3]);
                mma16816(c1f, afr[1][1], bA[2], bA[3]);
                mma16816(c0f, afr[0][2], bB[0], bB[1]);
                mma16816(c1f, afr[1][2], bB[0], bB[1]);
                mma16816(c0f, afr[0][3], bB[2], bB[3]);
                mma16816(c1f, afr[1][3], bB[2], bB[3]);

                eA[h * 2 + 0] = ex2_bf16x2(cvt_bf16x2(c0f[0], c0f[1]));   // row g
                eA[h * 2 + 1] = ex2_bf16x2(cvt_bf16x2(c0f[2], c0f[3]));   // row g+8
                eB[h * 2 + 0] = ex2_bf16x2(cvt_bf16x2(c1f[0], c1f[1]));   // row g+16
                eB[h * 2 + 1] = ex2_bf16x2(cvt_bf16x2(c1f[2], c1f[3]));   // row g+24
            }
            // row-sum via tensor pipe: C[m,n] += sum_k E[m,k] * 1
            mma16816(acc0, eA, ONESF, ONESF);
            mma16816(acc1, eB, ONESF, ONESF);
        }
        __syncthreads();
    }

    // ---- per-row accumulation: acc[0]/acc[2] hold full row sums (4 lanes identical) ----
    if ((lane & 3) == 0) {
        atomicAdd(&g_rowsum[rbase + g],      acc0[0]);
        atomicAdd(&g_rowsum[rbase + 8 + g],  acc0[2]);
        atomicAdd(&g_rowsum[rbase + 16 + g], acc1[0]);
        atomicAdd(&g_rowsum[rbase + 24 + g], acc1[2]);
    }

    // ---- inline finalize: last CTA reduces all rows ----
    __syncthreads();
    if (tid == 0) {
        __threadfence();
        unsigned int old = atomicAdd(&g_done, 1u);
        smflag = (old == (unsigned int)(gridDim.x * gridDim.y - 1)) ? 1 : 0;
    }
    __syncthreads();
    if (smflag) {
        const float cn2 = (float)(g_cost_sum / (double)M);
        const float alpha2 = 1.0f / (REGP * cn2);
        const float log_nu = -logf((float)M);
        double part = 0.0;
        for (int i = tid; i < N; i += THREADS) {
            float lse = -alpha2 * g_sqs[i] + log_nu + LN2 * (log2f(g_rowsum[i]) - SHIFT);
            part += (double)(-REGP * lse);
        }
        #pragma unroll
        for (int o = 16; o; o >>= 1) part += __shfl_xor_sync(0xffffffffu, part, o);
        if (lane == 0) atomicAdd(&g_result, part);
        __syncthreads();
        if (tid == 0)
            out[0] = (float)(g_result / (double)N + g_psi_sum / (double)M);
    }
}

extern "C" void kernel_launch(void* const* d_in, const int* in_sizes, int n_in,
                              void* d_out, int out_size) {
    const float* src = (const float*)d_in[0];   // [N, 64]
    const float* tgt = (const float*)d_in[1];   // [M, 64]
    const float* psi = (const float*)d_in[2];   // [M]
    int N = in_sizes[0] / DVAL;
    int M = in_sizes[2];

    k_pre<<<296, 256>>>(src, tgt, psi, N, M);

    dim3 grd(N / BLOCK_ROWS, JSPLIT);           // 16 x 9 = 144 CTAs, 1/SM
    k_main_mma<<<grd, THREADS>>>(psi, (float*)d_out, N, M);
}